// round 16
// baseline (speedup 1.0000x reference)
#include <cuda_runtime.h>

#define BB 4096
#define TT 100
#define FC1 752
#define KW 188         // k-range per warp (4 warps * 188 = 752)

__device__ __align__(16) float g_xc[BB * 256]; // [B][256]: x | user emb

// ---- packed f32x2 helpers ----
__device__ __forceinline__ unsigned long long fma2(unsigned long long a,
                                                   unsigned long long b,
                                                   unsigned long long c) {
    unsigned long long d;
    asm("fma.rn.f32x2 %0, %1, %2, %3;" : "=l"(d) : "l"(a), "l"(b), "l"(c));
    return d;
}
__device__ __forceinline__ unsigned long long dup2(float x) {
    unsigned long long r;
    asm("mov.b64 %0, {%1, %1};" : "=l"(r) : "f"(x));
    return r;
}
__device__ __forceinline__ float2 unpk(unsigned long long v) {
    float2 f;
    asm("mov.b64 {%0, %1}, %2;" : "=f"(f.x), "=f"(f.y) : "l"(v));
    return f;
}

// ======= K1: fused conv+FC1, 8 rows/block, 4 warps (co-residable) ==========
#define NT1 128

__device__ __forceinline__ void btf32(float (&v)[32], int lane) {
    #pragma unroll
    for (int s = 16; s >= 1; s >>= 1) {
        const bool up = (lane & s) != 0;
        #pragma unroll
        for (int i = 0; i < s; i++) {
            float lo = v[i], hi = v[i + s];
            float give = up ? lo : hi;
            float r = __shfl_xor_sync(0xffffffffu, give, s);
            v[i] = (up ? hi : lo) + r;
        }
    }
}

template <int L_, int T0, int NT>
__device__ __forceinline__ void hor_group(const float4 (&e)[5],
                                          const float4* __restrict__ wh4,
                                          const float* __restrict__ d_bh,
                                          float* zrow,
                                          int lane)
{
    constexpr int LOUT = 6 - L_;
    constexpr int ZOFF = 512 + 16 * (6 * (L_ - 1) - (L_ * (L_ - 1)) / 2);
    float v[32];
    if (NT == 1) {
        #pragma unroll
        for (int i = 16; i < 32; i++) v[i] = 0.f;
    }
    #pragma unroll
    for (int f = 0; f < 16; f++) {
        float4 w[L_];
        #pragma unroll
        for (int s = 0; s < L_; s++)
            w[s] = __ldg(wh4 + ((L_ - 1) * 80 + f * 5 + s) * 32 + lane);
        #pragma unroll
        for (int tp = 0; tp < NT; tp++) {
            const int a = (NT == 2) ? (f * 2 + tp) : f;
            float acc = 0.f;
            #pragma unroll
            for (int s = 0; s < L_; s++) {
                const float4 ww = w[s];
                const float4 ee = e[T0 + tp + s];
                acc = fmaf(ee.x, ww.x, acc); acc = fmaf(ee.y, ww.y, acc);
                acc = fmaf(ee.z, ww.z, acc); acc = fmaf(ee.w, ww.w, acc);
            }
            v[a] = acc;
        }
    }
    btf32(v, lane);
    if (NT == 2 || lane < 16) {
        const int f = (NT == 2) ? (lane >> 1) : lane;
        const int t = T0 + ((NT == 2) ? (lane & 1) : 0);
        const float b = __ldg(d_bh + (L_ - 1) * 16 + f);
        zrow[ZOFF + f * LOUT + t] = fmaxf(v[0] + b, 0.f);
    }
}

__global__ void __launch_bounds__(NT1)
caser_feat_kernel(int row_base,
                  const int* __restrict__ d_seq,
                  const int* __restrict__ d_user,
                  const float* __restrict__ d_item_table,
                  const float* __restrict__ d_user_table,
                  const float* __restrict__ d_Wv,
                  const float* __restrict__ d_bv,
                  const float* __restrict__ d_Wh,
                  const float* __restrict__ d_bh,
                  const float* __restrict__ d_W1,
                  const float* __restrict__ d_b1)
{
    __shared__ __align__(16) float  s_z[8][FC1];          // 24064 B
    __shared__ __align__(16) float4 s_red[4][8][32];      // 16384 B

    const int lane = threadIdx.x & 31;
    const int wid  = threadIdx.x >> 5;                    // 0..3
    const int base = row_base + blockIdx.x * 8;

    // ---------------- conv phase: 2 rows per warp, sequential passes --------
    #pragma unroll 1
    for (int pass = 0; pass < 2; pass++) {
        const int r   = wid * 2 + pass;                   // 0..7
        const int row = base + r;

        float4 e[5];
        #pragma unroll
        for (int t = 0; t < 5; t++) {
            int idx = __ldg(d_seq + row * 5 + t);
            e[t] = __ldg((const float4*)d_item_table + (size_t)idx * 32 + lane);
        }
        {
            int u = __ldg(d_user + row);
            ((float4*)g_xc)[(size_t)row * 64 + 32 + lane] =
                __ldg((const float4*)d_user_table + (size_t)u * 32 + lane);
        }

        float* zrow = s_z[r];

        #pragma unroll
        for (int v = 0; v < 4; v++) {
            float b = __ldg(d_bv + v);
            float4 acc = {b, b, b, b};
            #pragma unroll
            for (int t = 0; t < 5; t++) {
                float wv = __ldg(d_Wv + v * 5 + t);
                acc.x = fmaf(e[t].x, wv, acc.x); acc.y = fmaf(e[t].y, wv, acc.y);
                acc.z = fmaf(e[t].z, wv, acc.z); acc.w = fmaf(e[t].w, wv, acc.w);
            }
            ((float4*)zrow)[v * 32 + lane] = acc;
        }

        const float4* wh4 = (const float4*)d_Wh;
        hor_group<1, 0, 2>(e, wh4, d_bh, zrow, lane);
        hor_group<1, 2, 2>(e, wh4, d_bh, zrow, lane);
        hor_group<1, 4, 1>(e, wh4, d_bh, zrow, lane);
        hor_group<2, 0, 2>(e, wh4, d_bh, zrow, lane);
        hor_group<2, 2, 2>(e, wh4, d_bh, zrow, lane);
        hor_group<3, 0, 2>(e, wh4, d_bh, zrow, lane);
        hor_group<3, 2, 1>(e, wh4, d_bh, zrow, lane);
        hor_group<4, 0, 2>(e, wh4, d_bh, zrow, lane);
        hor_group<5, 0, 1>(e, wh4, d_bh, zrow, lane);
    }
    __syncthreads();

    // ---------------- FC1 phase: k-split across 4 warps ---------------------
    {
        const int k0 = wid * KW;
        const float4* w1v = (const float4*)d_W1 + (size_t)k0 * 32;

        unsigned long long aL[8], aH[8];
        #pragma unroll
        for (int r = 0; r < 8; r++) { aL[r] = 0; aH[r] = 0; }

        #pragma unroll 2
        for (int k = 0; k < KW; k++) {
            float4 w4 = __ldg(w1v + k * 32 + lane);
            union { float4 f; unsigned long long u[2]; } wu;
            wu.f = w4;
            #pragma unroll
            for (int r = 0; r < 8; r++) {
                unsigned long long d = dup2(s_z[r][k0 + k]);
                aL[r] = fma2(wu.u[0], d, aL[r]);
                aH[r] = fma2(wu.u[1], d, aH[r]);
            }
        }

        #pragma unroll
        for (int r = 0; r < 8; r++) {
            float2 lo = unpk(aL[r]);
            float2 hi = unpk(aH[r]);
            float4 p; p.x = lo.x; p.y = lo.y; p.z = hi.x; p.w = hi.y;
            s_red[wid][r][lane] = p;
        }
    }
    __syncthreads();

    // ---------------- reduce 4 partials, bias, relu, store ------------------
    {
        float4 b4 = __ldg((const float4*)d_b1 + lane);
        #pragma unroll
        for (int pass = 0; pass < 2; pass++) {
            const int r = wid * 2 + pass;
            float4 acc = s_red[0][r][lane];
            #pragma unroll
            for (int w = 1; w < 4; w++) {
                float4 p = s_red[w][r][lane];
                acc.x += p.x; acc.y += p.y; acc.z += p.z; acc.w += p.w;
            }
            float4 x;
            x.x = fmaxf(acc.x + b4.x, 0.f);
            x.y = fmaxf(acc.y + b4.y, 0.f);
            x.z = fmaxf(acc.z + b4.z, 0.f);
            x.w = fmaxf(acc.w + b4.w, 0.f);
            ((float4*)g_xc)[(size_t)(base + r) * 64 + lane] = x;
        }
    }
}

// ================= K2: scoring ==============================================
#define NT3 256

__global__ void __launch_bounds__(NT3)
caser_score_kernel(int row_base,
                   const int* __restrict__ d_items,
                   const float* __restrict__ d_W2,
                   const float* __restrict__ d_b2,
                   float* __restrict__ d_out)
{
    const int wid  = threadIdx.x >> 5;
    const int lane = threadIdx.x & 31;
    const int row  = row_base + blockIdx.x * 2 + (wid >> 2);
    const int part = wid & 3;

    const float4* xc4 = ((const float4*)g_xc) + (size_t)row * 64;
    float4 c0 = xc4[lane];
    float4 c1 = xc4[lane + 32];

    const int* itp = d_items + (size_t)row * TT + part * 25;
    float* outp = d_out + (size_t)row * TT + part * 25;

    for (int t = 0; t < 25; t += 5) {
        int it[5];
        #pragma unroll
        for (int q = 0; q < 5; q++) it[q] = __ldg(itp + t + q);
        float acc[5];
        #pragma unroll
        for (int q = 0; q < 5; q++) {
            const float4* w2 = (const float4*)(d_W2 + (size_t)it[q] * 256);
            float4 a0 = __ldg(w2 + lane);
            float4 a1 = __ldg(w2 + lane + 32);
            acc[q] = a0.x * c0.x + a0.y * c0.y + a0.z * c0.z + a0.w * c0.w
                   + a1.x * c1.x + a1.y * c1.y + a1.z * c1.z + a1.w * c1.w;
        }
        #pragma unroll
        for (int q = 0; q < 5; q++)
            #pragma unroll
            for (int sft = 16; sft; sft >>= 1)
                acc[q] += __shfl_xor_sync(0xffffffffu, acc[q], sft);
        if (lane == 0) {
            #pragma unroll
            for (int q = 0; q < 5; q++)
                outp[t + q] = acc[q] + __ldg(d_b2 + it[q]);
        }
    }
}

// ================= launcher: 2-chunk pipelined graph ========================
#define HB (BB / 2)

static cudaStream_t g_s2 = 0;
static cudaEvent_t  g_e0 = 0, g_e1 = 0;

extern "C" void kernel_launch(void* const* d_in, const int* in_sizes, int n_in,
                              void* d_out, int out_size)
{
    const int*   seq        = (const int*)  d_in[0];
    const int*   user       = (const int*)  d_in[1];
    const int*   items      = (const int*)  d_in[2];
    const float* item_table = (const float*)d_in[3];
    const float* user_table = (const float*)d_in[4];
    const float* Wv         = (const float*)d_in[5];
    const float* bv         = (const float*)d_in[6];
    const float* Wh         = (const float*)d_in[7];
    const float* bh         = (const float*)d_in[8];
    const float* W1         = (const float*)d_in[9];
    const float* b1         = (const float*)d_in[10];
    const float* W2         = (const float*)d_in[11];
    const float* b2         = (const float*)d_in[12];
    (void)in_sizes; (void)n_in; (void)out_size;

    if (!g_s2) {
        cudaStreamCreateWithFlags(&g_s2, cudaStreamNonBlocking);
        cudaEventCreateWithFlags(&g_e0, cudaEventDisableTiming);
        cudaEventCreateWithFlags(&g_e1, cudaEventDisableTiming);
    }

    // chunk 0 features
    caser_feat_kernel<<<HB / 8, NT1>>>(0, seq, user, item_table, user_table,
                                       Wv, bv, Wh, bh, W1, b1);
    // fork: chunk 1 features overlap chunk 0 scoring
    cudaEventRecord(g_e0, 0);
    cudaStreamWaitEvent(g_s2, g_e0, 0);
    caser_feat_kernel<<<HB / 8, NT1, 0, g_s2>>>(HB, seq, user, item_table,
                                                user_table, Wv, bv, Wh, bh,
                                                W1, b1);
    caser_score_kernel<<<HB / 2, NT3>>>(0, items, W2, b2, (float*)d_out);
    // join
    cudaEventRecord(g_e1, g_s2);
    cudaStreamWaitEvent(0, g_e1, 0);
    caser_score_kernel<<<HB / 2, NT3>>>(HB, items, W2, b2, (float*)d_out);
}

// round 17
// speedup vs baseline: 1.2656x; 1.2656x over previous
#include <cuda_runtime.h>

#define BB 4096
#define TT 100
#define FC1 752
#define KW 94          // k-range per warp (8 warps * 94 = 752)

__device__ __align__(16) float g_xc[BB * 256]; // [B][256]: x | user emb

// ---- packed f32x2 helpers ----
__device__ __forceinline__ unsigned long long fma2(unsigned long long a,
                                                   unsigned long long b,
                                                   unsigned long long c) {
    unsigned long long d;
    asm("fma.rn.f32x2 %0, %1, %2, %3;" : "=l"(d) : "l"(a), "l"(b), "l"(c));
    return d;
}
__device__ __forceinline__ unsigned long long dup2(float x) {
    unsigned long long r;
    asm("mov.b64 %0, {%1, %1};" : "=l"(r) : "f"(x));
    return r;
}
__device__ __forceinline__ float2 unpk(unsigned long long v) {
    float2 f;
    asm("mov.b64 {%0, %1}, %2;" : "=f"(f.x), "=f"(f.y) : "l"(v));
    return f;
}

// Butterfly transpose-reduce: 31 shuffles; lane L's v[0] = total of slot L.
__device__ __forceinline__ void btf32(float (&v)[32], int lane) {
    #pragma unroll
    for (int s = 16; s >= 1; s >>= 1) {
        const bool up = (lane & s) != 0;
        #pragma unroll
        for (int i = 0; i < s; i++) {
            float lo = v[i], hi = v[i + s];
            float give = up ? lo : hi;
            float r = __shfl_xor_sync(0xffffffffu, give, s);
            v[i] = (up ? hi : lo) + r;
        }
    }
}

// ============ K1: fused conv + FC1 (8 rows/block, 8 warps) — R14 ============
#define NT1 256

template <int L_, int T0, int NT>
__device__ __forceinline__ void hor_group(const float4 (&e)[5],
                                          const float4* __restrict__ wh4,
                                          const float* __restrict__ d_bh,
                                          float* zrow,
                                          int lane)
{
    constexpr int LOUT = 6 - L_;
    constexpr int ZOFF = 512 + 16 * (6 * (L_ - 1) - (L_ * (L_ - 1)) / 2);
    float v[32];
    if (NT == 1) {
        #pragma unroll
        for (int i = 16; i < 32; i++) v[i] = 0.f;
    }
    #pragma unroll
    for (int f = 0; f < 16; f++) {
        float4 w[L_];
        #pragma unroll
        for (int s = 0; s < L_; s++)
            w[s] = __ldg(wh4 + ((L_ - 1) * 80 + f * 5 + s) * 32 + lane);
        #pragma unroll
        for (int tp = 0; tp < NT; tp++) {
            const int a = (NT == 2) ? (f * 2 + tp) : f;
            float acc = 0.f;
            #pragma unroll
            for (int s = 0; s < L_; s++) {
                const float4 ww = w[s];
                const float4 ee = e[T0 + tp + s];
                acc = fmaf(ee.x, ww.x, acc); acc = fmaf(ee.y, ww.y, acc);
                acc = fmaf(ee.z, ww.z, acc); acc = fmaf(ee.w, ww.w, acc);
            }
            v[a] = acc;
        }
    }
    btf32(v, lane);
    if (NT == 2 || lane < 16) {
        const int f = (NT == 2) ? (lane >> 1) : lane;
        const int t = T0 + ((NT == 2) ? (lane & 1) : 0);
        const float b = __ldg(d_bh + (L_ - 1) * 16 + f);
        zrow[ZOFF + f * LOUT + t] = fmaxf(v[0] + b, 0.f);
    }
}

__global__ void __launch_bounds__(NT1)
caser_feat_kernel(const int* __restrict__ d_seq,
                  const int* __restrict__ d_user,
                  const float* __restrict__ d_item_table,
                  const float* __restrict__ d_user_table,
                  const float* __restrict__ d_Wv,
                  const float* __restrict__ d_bv,
                  const float* __restrict__ d_Wh,
                  const float* __restrict__ d_bh,
                  const float* __restrict__ d_W1,
                  const float* __restrict__ d_b1)
{
    __shared__ __align__(16) float  s_z[8][FC1];
    __shared__ __align__(16) float4 s_red[8][8][32];

    const int lane = threadIdx.x & 31;
    const int wid  = threadIdx.x >> 5;
    const int base = blockIdx.x * 8;
    const int row  = base + wid;

    // ---------------- conv phase ----------------
    float4 e[5];
    #pragma unroll
    for (int t = 0; t < 5; t++) {
        int idx = __ldg(d_seq + row * 5 + t);
        e[t] = __ldg((const float4*)d_item_table + (size_t)idx * 32 + lane);
    }
    {
        int u = __ldg(d_user + row);
        ((float4*)g_xc)[(size_t)row * 64 + 32 + lane] =
            __ldg((const float4*)d_user_table + (size_t)u * 32 + lane);
    }

    float* zrow = s_z[wid];

    #pragma unroll
    for (int v = 0; v < 4; v++) {
        float b = __ldg(d_bv + v);
        float4 acc = {b, b, b, b};
        #pragma unroll
        for (int t = 0; t < 5; t++) {
            float wv = __ldg(d_Wv + v * 5 + t);
            acc.x = fmaf(e[t].x, wv, acc.x); acc.y = fmaf(e[t].y, wv, acc.y);
            acc.z = fmaf(e[t].z, wv, acc.z); acc.w = fmaf(e[t].w, wv, acc.w);
        }
        ((float4*)zrow)[v * 32 + lane] = acc;
    }

    const float4* wh4 = (const float4*)d_Wh;
    hor_group<1, 0, 2>(e, wh4, d_bh, zrow, lane);
    hor_group<1, 2, 2>(e, wh4, d_bh, zrow, lane);
    hor_group<1, 4, 1>(e, wh4, d_bh, zrow, lane);
    hor_group<2, 0, 2>(e, wh4, d_bh, zrow, lane);
    hor_group<2, 2, 2>(e, wh4, d_bh, zrow, lane);
    hor_group<3, 0, 2>(e, wh4, d_bh, zrow, lane);
    hor_group<3, 2, 1>(e, wh4, d_bh, zrow, lane);
    hor_group<4, 0, 2>(e, wh4, d_bh, zrow, lane);
    hor_group<5, 0, 1>(e, wh4, d_bh, zrow, lane);
    __syncthreads();

    // ---------------- FC1 phase: k-split across warps ----------------
    {
        const int k0 = wid * KW;
        const float4* w1v = (const float4*)d_W1 + (size_t)k0 * 32;

        unsigned long long aL[8], aH[8];
        #pragma unroll
        for (int r = 0; r < 8; r++) { aL[r] = 0; aH[r] = 0; }

        #pragma unroll 4
        for (int k = 0; k < KW; k++) {
            float4 w4 = __ldg(w1v + k * 32 + lane);
            union { float4 f; unsigned long long u[2]; } wu;
            wu.f = w4;
            #pragma unroll
            for (int r = 0; r < 8; r++) {
                unsigned long long d = dup2(s_z[r][k0 + k]);
                aL[r] = fma2(wu.u[0], d, aL[r]);
                aH[r] = fma2(wu.u[1], d, aH[r]);
            }
        }

        #pragma unroll
        for (int r = 0; r < 8; r++) {
            float2 lo = unpk(aL[r]);
            float2 hi = unpk(aH[r]);
            float4 p; p.x = lo.x; p.y = lo.y; p.z = hi.x; p.w = hi.y;
            s_red[wid][r][lane] = p;
        }
    }
    __syncthreads();

    // ---------------- reduce, bias, relu, store ----------------
    {
        const int r = threadIdx.x >> 5;
        float4 acc = s_red[0][r][lane];
        #pragma unroll
        for (int w = 1; w < 8; w++) {
            float4 p = s_red[w][r][lane];
            acc.x += p.x; acc.y += p.y; acc.z += p.z; acc.w += p.w;
        }
        float4 b4 = __ldg((const float4*)d_b1 + lane);
        float4 x;
        x.x = fmaxf(acc.x + b4.x, 0.f);
        x.y = fmaxf(acc.y + b4.y, 0.f);
        x.z = fmaxf(acc.z + b4.z, 0.f);
        x.w = fmaxf(acc.w + b4.w, 0.f);
        ((float4*)g_xc)[(size_t)(base + r) * 64 + lane] = x;
    }
}

// ============ K2: scoring (butterfly reduce: 31 SHFL per 25 items) ==========
#define NT3 256

__global__ void __launch_bounds__(NT3)
caser_score_kernel(const int* __restrict__ d_items,
                   const float* __restrict__ d_W2,
                   const float* __restrict__ d_b2,
                   float* __restrict__ d_out)
{
    const int wid  = threadIdx.x >> 5;
    const int lane = threadIdx.x & 31;
    const int row  = blockIdx.x * 2 + (wid >> 2);
    const int part = wid & 3;

    const float4* xc4 = ((const float4*)g_xc) + (size_t)row * 64;
    float4 c0 = xc4[lane];
    float4 c1 = xc4[lane + 32];

    const int* itp = d_items + (size_t)row * TT + part * 25;
    float* outp = d_out + (size_t)row * TT + part * 25;

    float v[32];
    #pragma unroll
    for (int i = 25; i < 32; i++) v[i] = 0.f;

    #pragma unroll
    for (int t = 0; t < 25; t += 5) {
        int it[5];
        #pragma unroll
        for (int q = 0; q < 5; q++) it[q] = __ldg(itp + t + q);
        #pragma unroll
        for (int q = 0; q < 5; q++) {
            const float4* w2 = (const float4*)(d_W2 + (size_t)it[q] * 256);
            float4 a0 = __ldg(w2 + lane);
            float4 a1 = __ldg(w2 + lane + 32);
            v[t + q] = a0.x * c0.x + a0.y * c0.y + a0.z * c0.z + a0.w * c0.w
                     + a1.x * c1.x + a1.y * c1.y + a1.z * c1.z + a1.w * c1.w;
        }
    }

    btf32(v, lane);   // lane L: v[0] = score of item L (L < 25)

    if (lane < 25) {
        int itm = __ldg(itp + lane);
        outp[lane] = v[0] + __ldg(d_b2 + itm);
    }
}

extern "C" void kernel_launch(void* const* d_in, const int* in_sizes, int n_in,
                              void* d_out, int out_size)
{
    const int*   seq        = (const int*)  d_in[0];
    const int*   user       = (const int*)  d_in[1];
    const int*   items      = (const int*)  d_in[2];
    const float* item_table = (const float*)d_in[3];
    const float* user_table = (const float*)d_in[4];
    const float* Wv         = (const float*)d_in[5];
    const float* bv         = (const float*)d_in[6];
    const float* Wh         = (const float*)d_in[7];
    const float* bh         = (const float*)d_in[8];
    const float* W1         = (const float*)d_in[9];
    const float* b1         = (const float*)d_in[10];
    const float* W2         = (const float*)d_in[11];
    const float* b2         = (const float*)d_in[12];
    (void)in_sizes; (void)n_in; (void)out_size;

    caser_feat_kernel<<<BB / 8, NT1>>>(seq, user, item_table, user_table,
                                       Wv, bv, Wh, bh, W1, b1);
    caser_score_kernel<<<BB / 2, NT3>>>(items, W2, b2, (float*)d_out);
}